// round 1
// baseline (speedup 1.0000x reference)
#include <cuda_runtime.h>

// DirichletLoss: ball query (r=0.15, K=32 nearest within radius) + neighbor
// feature variance, mean over all B*N queries, scaled by 0.5.
//
// Pipeline (all graph-capturable, scratch in __device__ globals):
//   k_zero    : reset cell counters
//   k_count   : histogram points into 7x7x7 grid per batch (cell = r)
//   k_scan    : 1-CTA Hillis-Steele exclusive offsets over 8*343 cells
//   k_scatter : counting-sort points into float4(x,y,z,f), cell-major
//   k_main    : warp-per-query; lane-distributed sorted top-32 by distance
//   k_reduce  : deterministic single-CTA sum -> 0.5 * mean

#define FULLMASK 0xFFFFFFFFu

constexpr int   B    = 8;
constexpr int   N    = 4096;
constexpr int   BN   = B * N;
constexpr int   GD   = 7;            // grid cells per axis (cell size = r)
constexpr int   NC   = GD * GD * GD; // 343 cells per batch
constexpr int   TOTC = B * NC;       // 2744 cells total
constexpr float R2       = 0.15f * 0.15f;
constexpr float INV_CELL = 1.0f / 0.15f;
constexpr float BIGF     = 3.0e38f;

__device__ int    g_count[TOTC];
__device__ int    g_fill [TOTC];
__device__ int    g_off  [TOTC + 1];
__device__ float4 g_pts  [BN];       // (x, y, z, f) sorted by global cell id
__device__ float  g_var  [BN];       // per-query variance sums

__device__ __forceinline__ int cell1(float x) {
    int c = (int)(x * INV_CELL);
    c = c < 0 ? 0 : c;
    return c > GD - 1 ? GD - 1 : c;
}

__global__ void k_zero() {
    int i = blockIdx.x * blockDim.x + threadIdx.x;
    if (i < TOTC) { g_count[i] = 0; g_fill[i] = 0; }
}

__global__ void k_count(const float* __restrict__ pos) {
    int i = blockIdx.x * blockDim.x + threadIdx.x;
    if (i >= BN) return;
    float x = pos[3 * i], y = pos[3 * i + 1], z = pos[3 * i + 2];
    int b   = i >> 12;
    int cid = (cell1(z) * GD + cell1(y)) * GD + cell1(x);
    atomicAdd(&g_count[b * NC + cid], 1);
}

// Inclusive Hillis-Steele scan over TOTC=2744 counts in shared memory.
__global__ void k_scan() {
    __shared__ int s[TOTC];
    int t = threadIdx.x;  // blockDim.x == 1024
    for (int i = t; i < TOTC; i += 1024) s[i] = g_count[i];
    __syncthreads();
    for (int d = 1; d < TOTC; d <<= 1) {
        int v[3]; int c = 0;
        for (int i = t; i < TOTC; i += 1024) v[c++] = (i >= d) ? s[i - d] : 0;
        __syncthreads();
        c = 0;
        for (int i = t; i < TOTC; i += 1024) s[i] += v[c++];
        __syncthreads();
    }
    for (int i = t; i < TOTC; i += 1024) g_off[i + 1] = s[i];
    if (t == 0) g_off[0] = 0;
}

__global__ void k_scatter(const float* __restrict__ pos,
                          const float* __restrict__ f) {
    int i = blockIdx.x * blockDim.x + threadIdx.x;
    if (i >= BN) return;
    float x = pos[3 * i], y = pos[3 * i + 1], z = pos[3 * i + 2];
    int b   = i >> 12;
    int gc  = b * NC + (cell1(z) * GD + cell1(y)) * GD + cell1(x);
    int dst = g_off[gc] + atomicAdd(&g_fill[gc], 1);
    g_pts[dst] = make_float4(x, y, z, f[i]);
}

// One warp per query. Lane ℓ holds the ℓ-th smallest (d2, f) pair found so
// far (sorted ascending across lanes). Insertion = warp-collective shift-up.
__global__ void __launch_bounds__(256) k_main() {
    int lane = threadIdx.x & 31;
    int wid  = threadIdx.x >> 5;
    int q    = blockIdx.x * 8 + wid;           // BN/8 blocks of 8 warps

    float4 p = g_pts[q];
    int b  = q >> 12;                          // sorted array is batch-contiguous
    int cx = cell1(p.x), cy = cell1(p.y), cz = cell1(p.z);

    float kd = BIGF;      // distance key, ascending by lane
    float kf = 0.0f;      // paired neighbor f
    float cutoff = BIGF;  // current 32nd-smallest (lane 31's kd)

    int xlo = cx > 0 ? cx - 1 : 0,      xhi = cx < GD - 1 ? cx + 1 : GD - 1;
    int ylo = cy > 0 ? cy - 1 : 0,      yhi = cy < GD - 1 ? cy + 1 : GD - 1;
    int zlo = cz > 0 ? cz - 1 : 0,      zhi = cz < GD - 1 ? cz + 1 : GD - 1;

    for (int z = zlo; z <= zhi; z++) {
        for (int y = ylo; y <= yhi; y++) {
            int rowbase = b * NC + (z * GD + y) * GD;
            int s0 = g_off[rowbase + xlo];
            int s1 = g_off[rowbase + xhi + 1];  // contiguous 3-cell row
            for (int base = s0; base < s1; base += 32) {
                int j = base + lane;
                float d2 = BIGF, fj = 0.0f;
                if (j < s1) {
                    float4 c = g_pts[j];
                    float dx = c.x - p.x, dy = c.y - p.y, dz2 = c.z - p.z;
                    d2 = fmaf(dx, dx, fmaf(dy, dy, dz2 * dz2));
                    fj = c.w;
                }
                unsigned want = __ballot_sync(FULLMASK, d2 <= R2 && d2 < cutoff);
                while (want) {
                    int src  = __ffs(want) - 1;
                    float v  = __shfl_sync(FULLMASK, d2, src);
                    float fv = __shfl_sync(FULLMASK, fj, src);
                    // distributed sorted insert of (v, fv), evicting lane31
                    float pd = __shfl_up_sync(FULLMASK, kd, 1);
                    float pf = __shfl_up_sync(FULLMASK, kf, 1);
                    if (lane == 0) pd = -BIGF;
                    if (kd > v) {
                        bool pg = pd > v;
                        kd = pg ? pd : v;
                        kf = pg ? pf : fv;
                    }
                    cutoff = __shfl_sync(FULLMASK, kd, 31);
                    want = (want & ~(1u << src)) &
                           __ballot_sync(FULLMASK, d2 < cutoff);
                }
            }
        }
    }

    float t = (kd <= R2) ? (p.w - kf) * (p.w - kf) : 0.0f;
    #pragma unroll
    for (int o = 16; o; o >>= 1) t += __shfl_xor_sync(FULLMASK, t, o);
    if (lane == 0) g_var[q] = t;
}

__global__ void k_reduce(float* __restrict__ out) {
    __shared__ double s[1024];
    int t = threadIdx.x;
    double a = 0.0;
    for (int i = t; i < BN; i += 1024) a += (double)g_var[i];
    s[t] = a;
    __syncthreads();
    for (int d = 512; d; d >>= 1) {
        if (t < d) s[t] += s[t + d];
        __syncthreads();
    }
    if (t == 0) out[0] = (float)(0.5 * s[0] / (double)BN);
}

extern "C" void kernel_launch(void* const* d_in, const int* in_sizes, int n_in,
                              void* d_out, int out_size) {
    const float* pos = (const float*)d_in[0];
    const float* f   = (const float*)d_in[1];
    if (n_in >= 2 && in_sizes[0] == BN && in_sizes[1] == 3 * BN) {
        // defensive: inputs arrived as (f, pos)
        const float* tmp = pos; pos = f; f = tmp;
    }
    float* out = (float*)d_out;

    k_zero<<<(TOTC + 255) / 256, 256>>>();
    k_count<<<BN / 256, 256>>>(pos);
    k_scan<<<1, 1024>>>();
    k_scatter<<<BN / 256, 256>>>(pos, f);
    k_main<<<BN / 8, 256>>>();
    k_reduce<<<1, 1024>>>(out);
}

// round 4
// speedup vs baseline: 1.2042x; 1.2042x over previous
#include <cuda_runtime.h>

// DirichletLoss: ball query (r=0.15, K=32 nearest within radius) + neighbor
// feature variance, mean over all B*N queries, *0.5.
//
// 3-kernel pipeline (graph-capturable, scratch in __device__ globals):
//   k_build  : per-batch block — smem histogram, single-warp shfl scan,
//              counting-sort into float4(x,y,z,f) cell-major; global offsets
//   k_main   : warp-per-query, two passes:
//              A) key-only lane-distributed sorted top-32 distances
//              B) rescan candidates, accumulate (f_i-f_j)^2 for d2<=cutoff
//              block partial reduction (8 warps -> 1 value)
//   k_reduce : deterministic single-CTA sum -> 0.5 * mean
//
// All candidate ranges are clamped so every loop terminates even if the
// offset table were corrupt (turns any build bug into a visible wrong
// answer rather than a device hang).

#define FULLMASK 0xFFFFFFFFu

constexpr int   B    = 8;
constexpr int   N    = 4096;
constexpr int   BN   = B * N;
constexpr int   GD   = 7;            // cells per axis (cell size = r = 0.15)
constexpr int   NC   = GD * GD * GD; // 343 cells per batch
constexpr int   TOTC = B * NC;
constexpr int   NBLK = BN / 8;       // k_main blocks (8 warps each)
constexpr float R2       = 0.15f * 0.15f;
constexpr float INV_CELL = 1.0f / 0.15f;
constexpr float BIGF     = 3.0e38f;

__device__ int    g_off[TOTC + 1];
__device__ float4 g_pts[BN];         // (x,y,z,f) sorted by global cell id
__device__ float  g_var[NBLK];       // per-block partial sums

__device__ __forceinline__ int cell1(float x) {
    int c = (int)(x * INV_CELL);
    c = c < 0 ? 0 : c;
    return c > GD - 1 ? GD - 1 : c;
}

// One block per batch: histogram -> warp-0 scan -> scatter.
__global__ void __launch_bounds__(1024) k_build(const float* __restrict__ pos,
                                                const float* __restrict__ f) {
    __shared__ int cnt[NC];
    __shared__ int cur[NC];          // exclusive offsets -> fill cursors
    int b = blockIdx.x, t = threadIdx.x;
    int base = b * N;

    for (int i = t; i < NC; i += 1024) cnt[i] = 0;
    __syncthreads();

    float mx[4], my[4], mz[4], mf[4];
    int   mc[4];
    #pragma unroll
    for (int k = 0; k < 4; k++) {
        int gi = base + t + k * 1024;
        float x = pos[3 * gi], y = pos[3 * gi + 1], z = pos[3 * gi + 2];
        mx[k] = x; my[k] = y; mz[k] = z; mf[k] = f[gi];
        int c = (cell1(z) * GD + cell1(y)) * GD + cell1(x);
        mc[k] = c;
        atomicAdd(&cnt[c], 1);
    }
    __syncthreads();

    // Single-warp exclusive scan over NC=343 counts (11 chunks of 32).
    if (t < 32) {
        int carry = 0;
        for (int c0 = 0; c0 < NC; c0 += 32) {
            int i = c0 + t;
            int x = (i < NC) ? cnt[i] : 0;
            int v = x;
            #pragma unroll
            for (int d = 1; d < 32; d <<= 1) {
                int u = __shfl_up_sync(FULLMASK, v, d);
                if (t >= d) v += u;
            }
            if (i < NC) cur[i] = carry + v - x;            // exclusive
            carry += __shfl_sync(FULLMASK, v, 31);         // chunk total
        }
    }
    __syncthreads();

    if (t < NC) g_off[b * NC + t] = base + cur[t];
    if (b == B - 1 && t == 0) g_off[TOTC] = BN;
    __syncthreads();

    #pragma unroll
    for (int k = 0; k < 4; k++) {
        int dst = base + atomicAdd(&cur[mc[k]], 1);
        if (dst >= 0 && dst < BN)
            g_pts[dst] = make_float4(mx[k], my[k], mz[k], mf[k]);
    }
}

// One warp per query.
__global__ void __launch_bounds__(256) k_main() {
    __shared__ float swarp[8];
    int lane = threadIdx.x & 31;
    int wid  = threadIdx.x >> 5;
    int q    = blockIdx.x * 8 + wid;

    float4 p = g_pts[q];
    int b  = q >> 12;                 // sorted array stays batch-contiguous
    int cx = cell1(p.x), cy = cell1(p.y), cz = cell1(p.z);
    int xlo = cx > 0 ? cx - 1 : 0, xhi = cx < GD - 1 ? cx + 1 : GD - 1;
    int zlo = cz > 0 ? cz - 1 : 0, zhi = cz < GD - 1 ? cz + 1 : GD - 1;
    int ylo = cy > 0 ? cy - 1 : 0, yhi = cy < GD - 1 ? cy + 1 : GD - 1;

    float kd = BIGF;                  // lane-sorted ascending distance keys
    float cutoff = BIGF;

    // Pass A: center row first so the cutoff tightens early.
    const int dzs[3] = {0, -1, 1};
    const int dys[3] = {0, -1, 1};
    #pragma unroll
    for (int zi = 0; zi < 3; zi++) {
        int z = cz + dzs[zi];
        if (z < 0 || z >= GD) continue;
        #pragma unroll
        for (int yi = 0; yi < 3; yi++) {
            int y = cy + dys[yi];
            if (y < 0 || y >= GD) continue;
            int rb = b * NC + (z * GD + y) * GD;
            int s0 = g_off[rb + xlo];
            int s1 = g_off[rb + xhi + 1];          // contiguous 3-cell row
            s0 = s0 < 0 ? 0 : s0;                  // termination guards
            s1 = s1 > BN ? BN : s1;
            if (s1 < s0) s1 = s0;
            for (int base0 = s0; base0 < s1; base0 += 32) {
                int j = base0 + lane;
                float d2 = BIGF;
                if (j < s1) {
                    float4 c = g_pts[j];
                    float dx = c.x - p.x, dy = c.y - p.y, dz = c.z - p.z;
                    d2 = fmaf(dx, dx, fmaf(dy, dy, dz * dz));
                }
                unsigned want =
                    __ballot_sync(FULLMASK, d2 <= R2 && d2 < cutoff);
                if (want) {
                    do {
                        int src = __ffs(want) - 1;
                        want &= want - 1;
                        float v  = __shfl_sync(FULLMASK, d2, src);
                        float pd = __shfl_up_sync(FULLMASK, kd, 1);
                        if (lane == 0) pd = -BIGF;
                        if (kd > v) kd = fmaxf(pd, v);   // sorted insert
                    } while (want);
                    cutoff = __shfl_sync(FULLMASK, kd, 31);
                }
            }
        }
    }

    // Final selection threshold: 32nd-smallest distance, capped at R2.
    float cutB = fminf(cutoff, R2);

    // Pass B: rescan (L1-hot) and accumulate feature variance.
    float acc = 0.0f;
    for (int z = zlo; z <= zhi; z++) {
        for (int y = ylo; y <= yhi; y++) {
            int rb = b * NC + (z * GD + y) * GD;
            int s0 = g_off[rb + xlo];
            int s1 = g_off[rb + xhi + 1];
            s0 = s0 < 0 ? 0 : s0;
            s1 = s1 > BN ? BN : s1;
            if (s1 < s0) s1 = s0;
            for (int base0 = s0; base0 < s1; base0 += 32) {
                int j = base0 + lane;
                if (j < s1) {
                    float4 c = g_pts[j];
                    float dx = c.x - p.x, dy = c.y - p.y, dz = c.z - p.z;
                    float d2 = fmaf(dx, dx, fmaf(dy, dy, dz * dz));
                    if (d2 <= cutB) {
                        float df = p.w - c.w;
                        acc = fmaf(df, df, acc);
                    }
                }
            }
        }
    }

    #pragma unroll
    for (int o = 16; o; o >>= 1) acc += __shfl_xor_sync(FULLMASK, acc, o);
    if (lane == 0) swarp[wid] = acc;
    __syncthreads();
    if (threadIdx.x == 0) {
        float s = 0.0f;
        #pragma unroll
        for (int w = 0; w < 8; w++) s += swarp[w];
        g_var[blockIdx.x] = s;
    }
}

__global__ void k_reduce(float* __restrict__ out) {
    __shared__ double s[1024];
    int t = threadIdx.x;
    double a = 0.0;
    for (int i = t; i < NBLK; i += 1024) a += (double)g_var[i];
    s[t] = a;
    __syncthreads();
    for (int d = 512; d; d >>= 1) {
        if (t < d) s[t] += s[t + d];
        __syncthreads();
    }
    if (t == 0) out[0] = (float)(0.5 * s[0] / (double)BN);
}

extern "C" void kernel_launch(void* const* d_in, const int* in_sizes, int n_in,
                              void* d_out, int out_size) {
    const float* pos = (const float*)d_in[0];
    const float* f   = (const float*)d_in[1];
    if (n_in >= 2 && in_sizes[0] == BN && in_sizes[1] == 3 * BN) {
        const float* tmp = pos; pos = f; f = tmp;   // defensive input order
    }
    float* out = (float*)d_out;

    k_build<<<B, 1024>>>(pos, f);
    k_main<<<NBLK, 256>>>();
    k_reduce<<<1, 1024>>>(out);
}